// round 12
// baseline (speedup 1.0000x reference)
#include <cuda_runtime.h>
#include <cuda_bf16.h>
#include <cstdint>

#define Bb 8
#define Nn 1024
#define Ee 10
#define EPAD 16
#define NCH 32
#define KS 4
#define KSL 256

__device__ float g_Ppart[Bb * NCH * Nn];
__device__ float g_Mpart[Bb * NCH * Nn];
__device__ float g_base[Bb * Nn * Ee];
__device__ __nv_bfloat16 g_Abf[(size_t)Bb * Nn * Nn];   // A in bf16 (loop-invariant)
__device__ float g_part[2][KS][Bb][Nn][16];             // GEMM partials ping-pong
__device__ float g_S[Bb * Ee];
__device__ float g_wp[Ee * Ee];

__device__ __forceinline__ uint32_t smem_u32(const void* p) {
    uint32_t a;
    asm("{ .reg .u64 t; cvta.to.shared.u64 t, %1; cvt.u32.u64 %0, t; }"
        : "=r"(a) : "l"(p));
    return a;
}

#define LDMX4(r0, r1, r2, r3, addr)                                           \
    asm volatile("ldmatrix.sync.aligned.m8n8.x4.shared.b16 {%0,%1,%2,%3}, [%4];" \
        : "=r"(r0), "=r"(r1), "=r"(r2), "=r"(r3) : "r"(addr))

__device__ __forceinline__ void mma_bf16(float* c, uint32_t a0, uint32_t a1,
                                         uint32_t a2, uint32_t a3,
                                         uint32_t b0, uint32_t b1) {
    asm volatile(
        "mma.sync.aligned.m16n8k16.row.col.f32.bf16.bf16.f32 "
        "{%0,%1,%2,%3}, {%4,%5,%6,%7}, {%8,%9}, {%0,%1,%2,%3};"
        : "+f"(c[0]), "+f"(c[1]), "+f"(c[2]), "+f"(c[3])
        : "r"(a0), "r"(a1), "r"(a2), "r"(a3), "r"(b0), "r"(b1));
}

// ---------------------------------------------------------------------------
// Convert A -> bf16 once.
// ---------------------------------------------------------------------------
__global__ void __launch_bounds__(256) conv_kernel(const float4* __restrict__ A) {
    size_t idx = (size_t)blockIdx.x * 256 + threadIdx.x;
    float4 v0 = A[2 * idx], v1 = A[2 * idx + 1];
    __nv_bfloat162 p0 = __floats2bfloat162_rn(v0.x, v0.y);
    __nv_bfloat162 p1 = __floats2bfloat162_rn(v0.z, v0.w);
    __nv_bfloat162 p2 = __floats2bfloat162_rn(v1.x, v1.y);
    __nv_bfloat162 p3 = __floats2bfloat162_rn(v1.z, v1.w);
    uint4 o;
    o.x = *reinterpret_cast<uint32_t*>(&p0);
    o.y = *reinterpret_cast<uint32_t*>(&p1);
    o.z = *reinterpret_cast<uint32_t*>(&p2);
    o.w = *reinterpret_cast<uint32_t*>(&p3);
    reinterpret_cast<uint4*>(g_Abf)[idx] = o;
}

// ---------------------------------------------------------------------------
// Colsum: P/M column sums of weights; stages Wp.
// ---------------------------------------------------------------------------
__global__ void __launch_bounds__(256) colsum_kernel(
    const float4* __restrict__ w4, const float* __restrict__ wp)
{
    int i4 = threadIdx.x, jc = blockIdx.x, b = blockIdx.y;
    if (jc == 0 && b == 0 && threadIdx.x < Ee * Ee)
        g_wp[threadIdx.x] = wp[threadIdx.x];

    const float4* p = w4 + ((size_t)(b * Nn + jc * 32) * 256) + i4;
    float4 sp = make_float4(0.f, 0.f, 0.f, 0.f);
    float4 sm = make_float4(0.f, 0.f, 0.f, 0.f);
#pragma unroll 8
    for (int j = 0; j < 32; j++) {
        float4 v = p[(size_t)j * 256];
        sp.x += fmaxf(v.x, 0.f); sm.x += fminf(v.x, 0.f);
        sp.y += fmaxf(v.y, 0.f); sm.y += fminf(v.y, 0.f);
        sp.z += fmaxf(v.z, 0.f); sm.z += fminf(v.z, 0.f);
        sp.w += fmaxf(v.w, 0.f); sm.w += fminf(v.w, 0.f);
    }
    ((float4*)g_Ppart)[(b * NCH + jc) * 256 + i4] = sp;
    ((float4*)g_Mpart)[(b * NCH + jc) * 256 + i4] = sm;
}

// ---------------------------------------------------------------------------
// Base: base[b,i,e]; zero g_part[0] and g_S. (h is derived by consumers.)
// ---------------------------------------------------------------------------
__global__ void __launch_bounds__(256) base_kernel(
    const float* __restrict__ feat,
    const float* __restrict__ ws,
    const float* __restrict__ wnb,
    const float* __restrict__ ew)
{
    int idx = blockIdx.x * 256 + threadIdx.x;   // 0..8191
    int b = idx >> 10, i = idx & 1023;
    if (idx < Bb * Ee) g_S[idx] = 0.f;
    {   // zero g_part[0]: 524288 floats = 131072 float4 / 8192 thr = 16 each
        float4* z = (float4*)&g_part[0][0][0][0][0];
#pragma unroll
        for (int k = 0; k < 16; k++)
            z[idx + k * 8192] = make_float4(0.f, 0.f, 0.f, 0.f);
    }

    float P = 0.f, M = 0.f;
#pragma unroll 8
    for (int c = 0; c < NCH; c++) {
        P += g_Ppart[(b * NCH + c) * Nn + i];
        M += g_Mpart[(b * NCH + c) * Nn + i];
    }
    float f = feat[idx];

    float ewv[Ee];
#pragma unroll
    for (int e = 0; e < Ee; e++) ewv[e] = ew[e];

#pragma unroll
    for (int e = 0; e < Ee; e++) {
        float cP = 0.f, cM = 0.f;
#pragma unroll
        for (int g = 0; g < Ee; g++) {
            float wv = wnb[e * Ee + g];
            cP += wv * fmaxf(ewv[g], 0.f);
            cM += wv * fminf(ewv[g], 0.f);
        }
        g_base[idx * Ee + e] = f * ws[e] + cP * P + cM * M;
    }
}

// ---------------------------------------------------------------------------
// mm_kernel: one K-slice of one iteration.
//   part_out[ks][b][i:64, 0:16] = A_bf16[64, ks-slice] @ h_slice^T
// where h is recomputed on the fly from part_in: h = Wp @ relu(base + sum part).
// grid (16 rowblocks, KS, Bb) = 512 CTAs x 256 thr (8 warps; 4 row-warps x 2
// k-halves, combined through smem). Exact ldmatrix/mma mappings from R9.
// ---------------------------------------------------------------------------
__global__ void __launch_bounds__(256, 3) mm_kernel(int src)
{
    __shared__ float wps[Ee * Ee];
    __shared__ __align__(16) __nv_bfloat16 hs[EPAD * KSL];   // 8 KB (reused for combine)
    __shared__ __align__(16) __nv_bfloat16 as[4 * 64 * 64];  // 32 KB
    int rb = blockIdx.x, ks = blockIdx.y, b = blockIdx.z;
    int tid = threadIdx.x;

    if (tid < Ee * Ee) wps[tid] = g_wp[tid];
    __syncthreads();

    // stage A: 4 chunks of 64 rows x 64 k, swizzled
    const uint4* Ag = (const uint4*)(g_Abf + ((size_t)b * Nn + rb * 64) * Nn);
    uint4* as4 = (uint4*)as;
#pragma unroll
    for (int p = 0; p < 8; p++) {
        int idx = tid + p * 256;              // 0..2047
        int ck = idx >> 9, rem = idx & 511;
        int r = rem >> 3, u = rem & 7;
        uint4 v = Ag[(size_t)r * 128 + ks * 32 + ck * 8 + u];
        as4[ck * 512 + r * 8 + (u ^ (r & 7))] = v;
    }

    // stage B: recompute h for j = ks*256 + tid, bf16, swizzled
    {
        int j = ks * KSL + tid;
        const float* bp = g_base + ((size_t)b * Nn + j) * Ee;
        float embv[Ee];
#pragma unroll
        for (int f = 0; f < Ee; f++) {
            float v = bp[f];
#pragma unroll
            for (int k2 = 0; k2 < KS; k2++)
                v += g_part[src][k2][b][j][f];
            embv[f] = fmaxf(v, 0.f);
        }
        int u = tid >> 3, lo = (tid & 7) * 2;
#pragma unroll
        for (int e = 0; e < EPAD; e++) {
            float hv = 0.f;
            if (e < Ee) {
#pragma unroll
                for (int f = 0; f < Ee; f++)
                    hv = fmaf(wps[e * Ee + f], embv[f], hv);
            }
            *(__nv_bfloat16*)((char*)hs + e * 512 + ((u ^ (e & 7)) << 4) + lo) =
                __float2bfloat16_rn(hv);
        }
    }
    __syncthreads();

    // mainloop: warp w = (wr row-group, wk k-half); each k-half = 2 chunks
    int lane = tid & 31, w = tid >> 5;
    int wr = w & 3, wk = w >> 2;
    int half = lane >> 4, lr = lane & 15, l7 = lane & 7;
    uint32_t a_base = smem_u32(as), b_base = smem_u32(hs);
    float c0[4] = {0.f, 0.f, 0.f, 0.f};
    float c1[4] = {0.f, 0.f, 0.f, 0.f};
#pragma unroll
    for (int cc = 0; cc < 2; cc++) {
        int ck = wk * 2 + cc;
        uint32_t a_row = a_base + (uint32_t)(ck * 8192 + (wr * 16 + lr) * 128);
#pragma unroll
        for (int s = 0; s < 4; s++) {
            int sg = ck * 4 + s;
            uint32_t aaddr = a_row + (uint32_t)((((2 * s + half) ^ l7) << 4));
            uint32_t baddr = b_base + (uint32_t)(lr * 512 +
                             (((2 * sg + half) ^ l7) << 4));
            uint32_t a0, a1, a2, a3, r0, r1, r2, r3;
            LDMX4(a0, a1, a2, a3, aaddr);
            LDMX4(r0, r1, r2, r3, baddr);
            mma_bf16(c0, a0, a1, a2, a3, r0, r2);   // cols 0-7
            mma_bf16(c1, a0, a1, a2, a3, r1, r3);   // cols 8-15
        }
    }

    // combine k-halves via smem (reuse hs region), then store partials
    __syncthreads();
    float* cs2 = (float*)hs;                      // 4 KB
    if (wk == 1) {
#pragma unroll
        for (int j2 = 0; j2 < 4; j2++) {
            cs2[(wr * 32 + lane) * 8 + j2] = c0[j2];
            cs2[(wr * 32 + lane) * 8 + 4 + j2] = c1[j2];
        }
    }
    __syncthreads();
    if (wk == 0) {
#pragma unroll
        for (int j2 = 0; j2 < 4; j2++) {
            c0[j2] += cs2[(wr * 32 + lane) * 8 + j2];
            c1[j2] += cs2[(wr * 32 + lane) * 8 + 4 + j2];
        }
        int g = lane >> 2, t = lane & 3;
        int ilo = rb * 64 + wr * 16 + g, ihi = ilo + 8;
        float* po = &g_part[src ^ 1][ks][b][0][0];
        *(float2*)&po[(size_t)ilo * 16 + 2 * t]     = make_float2(c0[0], c0[1]);
        *(float2*)&po[(size_t)ihi * 16 + 2 * t]     = make_float2(c0[2], c0[3]);
        *(float2*)&po[(size_t)ilo * 16 + 8 + 2 * t] = make_float2(c1[0], c1[1]);
        *(float2*)&po[(size_t)ihi * 16 + 8 + 2 * t] = make_float2(c1[2], c1[3]);
    }
}

// ---------------------------------------------------------------------------
// fin1: emb5 = relu(base + sum part[0]); write emb_out; accumulate g_S.
// ---------------------------------------------------------------------------
__global__ void __launch_bounds__(128) fin1_kernel(float* __restrict__ emb_out)
{
    __shared__ float sacc[Ee];
    int idx = blockIdx.x * 128 + threadIdx.x;
    int b = idx >> 10, i = idx & 1023;
    if (threadIdx.x < Ee) sacc[threadIdx.x] = 0.f;
    __syncthreads();

    const float* bp = g_base + (size_t)idx * Ee;
    float embv[Ee];
#pragma unroll
    for (int f = 0; f < Ee; f++) {
        float v = bp[f];
#pragma unroll
        for (int k2 = 0; k2 < KS; k2++) v += g_part[0][k2][b][i][f];
        embv[f] = fmaxf(v, 0.f);
        emb_out[(size_t)idx * Ee + f] = embv[f];
    }
#pragma unroll
    for (int e = 0; e < Ee; e++) {
        float v = embv[e];
        v += __shfl_xor_sync(0xffffffffu, v, 16);
        v += __shfl_xor_sync(0xffffffffu, v, 8);
        v += __shfl_xor_sync(0xffffffffu, v, 4);
        v += __shfl_xor_sync(0xffffffffu, v, 2);
        v += __shfl_xor_sync(0xffffffffu, v, 1);
        if ((threadIdx.x & 31) == 0) atomicAdd(&sacc[e], v);
    }
    __syncthreads();
    if (threadIdx.x < Ee) atomicAdd(&g_S[b * Ee + threadIdx.x], sacc[threadIdx.x]);
}

// ---------------------------------------------------------------------------
// fin2: q[b,i] = c_b + sum_e d_e * emb[b,i,e]
// ---------------------------------------------------------------------------
__global__ void __launch_bounds__(128) fin2_kernel(
    const float* __restrict__ emb,
    float* __restrict__ q,
    const float* __restrict__ wqr,
    const float* __restrict__ wall,
    const float* __restrict__ wact)
{
    int idx = blockIdx.x * 128 + threadIdx.x;
    int b = idx >> 10;
    float cb = 0.f;
#pragma unroll
    for (int f = 0; f < Ee; f++) {
        float t = 0.f;
#pragma unroll
        for (int e = 0; e < Ee; e++) t += wall[f * Ee + e] * g_S[b * Ee + e];
        cb += wqr[f] * t;
    }
    float qv = cb;
#pragma unroll
    for (int e = 0; e < Ee; e++) {
        float t = 0.f;
#pragma unroll
        for (int f = 0; f < Ee; f++) t += wqr[Ee + f] * wact[f * Ee + e];
        qv += t * emb[(size_t)idx * Ee + e];
    }
    q[idx] = qv;
}

extern "C" void kernel_launch(void* const* d_in, const int* in_sizes, int n_in,
                              void* d_out, int out_size) {
    const float* features       = (const float*)d_in[0];
    const float* weights        = (const float*)d_in[1];
    const float* adjacency      = (const float*)d_in[2];
    const float* w_selected     = (const float*)d_in[3];
    const float* w_nbpriors     = (const float*)d_in[4];
    const float* w_nbweights    = (const float*)d_in[5];
    const float* w_nbweights_ew = (const float*)d_in[6];
    const float* w_q_reduc      = (const float*)d_in[7];
    const float* w_q_allembed   = (const float*)d_in[8];
    const float* w_q_action     = (const float*)d_in[9];

    float* out = (float*)d_out;
    float* q = out;                  // [B,N]
    float* emb_out = out + Bb * Nn;  // [B,N,E]

    conv_kernel<<<4096, 256>>>((const float4*)adjacency);
    colsum_kernel<<<dim3(NCH, Bb), 256>>>((const float4*)weights, w_nbpriors);
    base_kernel<<<32, 256>>>(features, w_selected, w_nbweights, w_nbweights_ew);

    dim3 mg(16, KS, Bb);             // 512 CTAs
    mm_kernel<<<mg, 256>>>(0);       // iter 2: reads buf0(=0 => h1), writes buf1
    mm_kernel<<<mg, 256>>>(1);       // iter 3
    mm_kernel<<<mg, 256>>>(0);       // iter 4
    mm_kernel<<<mg, 256>>>(1);       // iter 5 -> buf0

    fin1_kernel<<<64, 128>>>(emb_out);
    fin2_kernel<<<64, 128>>>(emb_out, q, w_q_reduc, w_q_allembed, w_q_action);
}

// round 14
// speedup vs baseline: 1.8600x; 1.8600x over previous
#include <cuda_runtime.h>
#include <cuda_bf16.h>
#include <cstdint>

#define Bb 8
#define Nn 1024
#define Ee 10
#define EPAD 16
#define NCH 32

__device__ float g_Ppart[Bb * NCH * Nn];
__device__ float g_Mpart[Bb * NCH * Nn];
__device__ float g_base[Bb * Nn * Ee];
__device__ __nv_bfloat16 g_Abf[(size_t)Bb * Nn * Nn];    // A in bf16 (loop-invariant)
__device__ __nv_bfloat16 g_hbf[2][Bb * EPAD * Nn];       // h ping-pong [b][e(pad16)][i]
__device__ float g_S[Bb * Ee];
__device__ float g_wp[Ee * Ee];

__device__ __forceinline__ uint32_t smem_u32(const void* p) {
    uint32_t a;
    asm("{ .reg .u64 t; cvta.to.shared.u64 t, %1; cvt.u32.u64 %0, t; }"
        : "=r"(a) : "l"(p));
    return a;
}

#define LDMX4(r0, r1, r2, r3, addr)                                           \
    asm volatile("ldmatrix.sync.aligned.m8n8.x4.shared.b16 {%0,%1,%2,%3}, [%4];" \
        : "=r"(r0), "=r"(r1), "=r"(r2), "=r"(r3) : "r"(addr))

__device__ __forceinline__ void mma_bf16(float* c, uint32_t a0, uint32_t a1,
                                         uint32_t a2, uint32_t a3,
                                         uint32_t b0, uint32_t b1) {
    asm volatile(
        "mma.sync.aligned.m16n8k16.row.col.f32.bf16.bf16.f32 "
        "{%0,%1,%2,%3}, {%4,%5,%6,%7}, {%8,%9}, {%0,%1,%2,%3};"
        : "+f"(c[0]), "+f"(c[1]), "+f"(c[2]), "+f"(c[3])
        : "r"(a0), "r"(a1), "r"(a2), "r"(a3), "r"(b0), "r"(b1));
}

// ---------------------------------------------------------------------------
// Convert A -> bf16 once.
// ---------------------------------------------------------------------------
__global__ void __launch_bounds__(256) conv_kernel(const float4* __restrict__ A) {
    size_t idx = (size_t)blockIdx.x * 256 + threadIdx.x;
    float4 v0 = A[2 * idx], v1 = A[2 * idx + 1];
    __nv_bfloat162 p0 = __floats2bfloat162_rn(v0.x, v0.y);
    __nv_bfloat162 p1 = __floats2bfloat162_rn(v0.z, v0.w);
    __nv_bfloat162 p2 = __floats2bfloat162_rn(v1.x, v1.y);
    __nv_bfloat162 p3 = __floats2bfloat162_rn(v1.z, v1.w);
    uint4 o;
    o.x = *reinterpret_cast<uint32_t*>(&p0);
    o.y = *reinterpret_cast<uint32_t*>(&p1);
    o.z = *reinterpret_cast<uint32_t*>(&p2);
    o.w = *reinterpret_cast<uint32_t*>(&p3);
    reinterpret_cast<uint4*>(g_Abf)[idx] = o;
}

// ---------------------------------------------------------------------------
// Colsum: P/M column sums of weights; stages Wp.
// ---------------------------------------------------------------------------
__global__ void __launch_bounds__(256) colsum_kernel(
    const float4* __restrict__ w4, const float* __restrict__ wp)
{
    int i4 = threadIdx.x, jc = blockIdx.x, b = blockIdx.y;
    if (jc == 0 && b == 0 && threadIdx.x < Ee * Ee)
        g_wp[threadIdx.x] = wp[threadIdx.x];

    const float4* p = w4 + ((size_t)(b * Nn + jc * 32) * 256) + i4;
    float4 sp = make_float4(0.f, 0.f, 0.f, 0.f);
    float4 sm = make_float4(0.f, 0.f, 0.f, 0.f);
#pragma unroll 8
    for (int j = 0; j < 32; j++) {
        float4 v = p[(size_t)j * 256];
        sp.x += fmaxf(v.x, 0.f); sm.x += fminf(v.x, 0.f);
        sp.y += fmaxf(v.y, 0.f); sm.y += fminf(v.y, 0.f);
        sp.z += fmaxf(v.z, 0.f); sm.z += fminf(v.z, 0.f);
        sp.w += fmaxf(v.w, 0.f); sm.w += fminf(v.w, 0.f);
    }
    ((float4*)g_Ppart)[(b * NCH + jc) * 256 + i4] = sp;
    ((float4*)g_Mpart)[(b * NCH + jc) * 256 + i4] = sm;
}

// ---------------------------------------------------------------------------
// Base: base[b,i,e], emb1=relu(base), h1=Wp@emb1 -> g_hbf[0]; zero pads.
// ---------------------------------------------------------------------------
__global__ void __launch_bounds__(256) base_kernel(
    const float* __restrict__ feat,
    const float* __restrict__ ws,
    const float* __restrict__ wnb,
    const float* __restrict__ ew)
{
    int idx = blockIdx.x * 256 + threadIdx.x;
    int b = idx >> 10, i = idx & 1023;
    if (idx < Bb * Ee) g_S[idx] = 0.f;

    float P = 0.f, M = 0.f;
#pragma unroll 8
    for (int c = 0; c < NCH; c++) {
        P += g_Ppart[(b * NCH + c) * Nn + i];
        M += g_Mpart[(b * NCH + c) * Nn + i];
    }
    float f = feat[idx];

    float ewv[Ee];
#pragma unroll
    for (int e = 0; e < Ee; e++) ewv[e] = ew[e];

    float emb1[Ee];
#pragma unroll
    for (int e = 0; e < Ee; e++) {
        float cP = 0.f, cM = 0.f;
#pragma unroll
        for (int g = 0; g < Ee; g++) {
            float wv = wnb[e * Ee + g];
            cP += wv * fmaxf(ewv[g], 0.f);
            cM += wv * fminf(ewv[g], 0.f);
        }
        float basev = f * ws[e] + cP * P + cM * M;
        g_base[idx * Ee + e] = basev;
        emb1[e] = fmaxf(basev, 0.f);
    }
#pragma unroll
    for (int e = 0; e < Ee; e++) {
        float hv = 0.f;
#pragma unroll
        for (int g = 0; g < Ee; g++) hv += g_wp[e * Ee + g] * emb1[g];
        g_hbf[0][(b * EPAD + e) * Nn + i] = __float2bfloat16_rn(hv);
    }
#pragma unroll
    for (int e = Ee; e < EPAD; e++) {
        g_hbf[0][(b * EPAD + e) * Nn + i] = __float2bfloat16_rn(0.f);
        g_hbf[1][(b * EPAD + e) * Nn + i] = __float2bfloat16_rn(0.f);
    }
}

// ---------------------------------------------------------------------------
// Iteration (HMMA, stage-once / sync-free mainloop):
//   C[32,16] = A_rows[32,1024] @ h^T ; epilogue fused in-CTA.
// grid (32 rowblocks, 8 batches) = 256 CTAs x 256 thr (8 warps).
// Warp w: wr = w&1 (16-row group), wk = w>>1 (256-k slice).
// Dynamic smem: A 64 KB (16 chunks of 32rows x 64k, swizzled) | h^T 32 KB.
// After mainloop the h region is reused for the k-slice combine.
// ---------------------------------------------------------------------------
#define SM_AS 0
#define SM_HS 65536
#define SMEM_DYN (65536 + 32768)

__global__ void __launch_bounds__(256) iter_kernel(int src,
                                                   float* __restrict__ emb_out,
                                                   int last)
{
    extern __shared__ __align__(16) char smem[];
    __shared__ float wps[Ee * Ee];
    int rb = blockIdx.x, b = blockIdx.y;
    int tid = threadIdx.x;

    uint4* as4 = (uint4*)(smem + SM_AS);
    uint4* hs4 = (uint4*)(smem + SM_HS);

    // stage A rows [rb*32 .. +32): 4096 uint4, 16/thread, chunked+swizzled
    const uint4* Ag = (const uint4*)(g_Abf + ((size_t)b * Nn + rb * 32) * Nn);
#pragma unroll
    for (int p = 0; p < 16; p++) {
        int idx = tid + p * 256;               // 0..4095
        int r = idx >> 7, u7 = idx & 127;      // row, 16B-unit across k
        uint4 v = Ag[(size_t)r * 128 + u7];
        int ck = u7 >> 3, uu = u7 & 7;
        as4[ck * 256 + r * 8 + (uu ^ (r & 7))] = v;
    }
    // stage h^T: 2048 uint4, 8/thread, swizzled (R9 layout)
    const uint4* hb4 = (const uint4*)(g_hbf[src] + (size_t)b * EPAD * Nn);
#pragma unroll
    for (int p = 0; p < 8; p++) {
        int idx = tid + p * 256;
        int e = idx >> 7, u = idx & 127;
        hs4[e * 128 + (u ^ (e & 7))] = hb4[idx];
    }
    if (tid < Ee * Ee) wps[tid] = g_wp[tid];
    __syncthreads();

    // mainloop: sync-free, 16 k-steps of 16 per warp
    int lane = tid & 31, w = tid >> 5;
    int wr = w & 1, wk = w >> 1;
    int half = lane >> 4, lr = lane & 15, l7 = lane & 7;
    uint32_t a_base = smem_u32(smem + SM_AS);
    uint32_t b_base = smem_u32(smem + SM_HS);
    uint32_t a_row = a_base + (uint32_t)((wr * 16 + lr) * 128);
    uint32_t b_row = b_base + (uint32_t)(lr * 2048);

    float c0[4] = {0.f, 0.f, 0.f, 0.f};
    float c1[4] = {0.f, 0.f, 0.f, 0.f};
#pragma unroll
    for (int s = 0; s < 16; s++) {
        int sg = wk * 16 + s;                  // global 16-k step 0..63
        int ck = sg >> 2, su = sg & 3;
        uint32_t aaddr = a_row + (uint32_t)(ck * 4096 +
                         (((2 * su + half) ^ l7) << 4));
        uint32_t baddr = b_row + (uint32_t)(((2 * sg + half) ^ l7) << 4);
        uint32_t a0, a1, a2, a3, r0, r1, r2, r3;
        LDMX4(a0, a1, a2, a3, aaddr);
        LDMX4(r0, r1, r2, r3, baddr);
        mma_bf16(c0, a0, a1, a2, a3, r0, r2);  // cols 0-7
        mma_bf16(c1, a0, a1, a2, a3, r1, r3);  // cols 8-15
    }

    // combine k-slices through smem (reuse h region)
    __syncthreads();
    float* cs = (float*)(smem + SM_HS);        // [4 wk][2 wr][16 rows][16 cols]
    {
        float* po = cs + (wk * 2 + wr) * 256;
        int g = lane >> 2, t = lane & 3;
        po[g * 16 + 2 * t] = c0[0];           po[g * 16 + 2 * t + 1] = c0[1];
        po[(g + 8) * 16 + 2 * t] = c0[2];     po[(g + 8) * 16 + 2 * t + 1] = c0[3];
        po[g * 16 + 8 + 2 * t] = c1[0];       po[g * 16 + 8 + 2 * t + 1] = c1[1];
        po[(g + 8) * 16 + 8 + 2 * t] = c1[2]; po[(g + 8) * 16 + 8 + 2 * t + 1] = c1[3];
    }
    __syncthreads();

    // epilogue: thread t < 32 owns row t
    if (tid < 32) {
        int r = tid, i = rb * 32 + r;
        int wrr = r >> 4, rr = r & 15;
        const float* bp = g_base + ((size_t)(b * Nn) + i) * Ee;
        float embv[Ee];
#pragma unroll
        for (int e = 0; e < Ee; e++) {
            float v = bp[e];
#pragma unroll
            for (int k2 = 0; k2 < 4; k2++)
                v += cs[(k2 * 2 + wrr) * 256 + rr * 16 + e];
            embv[e] = fmaxf(v, 0.f);
        }
        __nv_bfloat16* ho = g_hbf[src ^ 1] + (size_t)b * EPAD * Nn + i;
#pragma unroll
        for (int e = 0; e < Ee; e++) {
            float hv = 0.f;
#pragma unroll
            for (int f = 0; f < Ee; f++) hv = fmaf(wps[e * Ee + f], embv[f], hv);
            ho[(size_t)e * Nn] = __float2bfloat16_rn(hv);
        }
        if (last) {
#pragma unroll
            for (int e = 0; e < Ee; e++) {
                emb_out[((size_t)(b * Nn) + i) * Ee + e] = embv[e];
                float v = embv[e];
                v += __shfl_xor_sync(0xffffffffu, v, 16);
                v += __shfl_xor_sync(0xffffffffu, v, 8);
                v += __shfl_xor_sync(0xffffffffu, v, 4);
                v += __shfl_xor_sync(0xffffffffu, v, 2);
                v += __shfl_xor_sync(0xffffffffu, v, 1);
                if (lane == 0) atomicAdd(&g_S[b * Ee + e], v);
            }
        }
    }
}

// ---------------------------------------------------------------------------
// Final: q[b,i] = c_b + sum_e d_e * emb[b,i,e]
// ---------------------------------------------------------------------------
__global__ void __launch_bounds__(128) final_kernel(
    const float* __restrict__ emb,
    float* __restrict__ q,
    const float* __restrict__ wqr,
    const float* __restrict__ wall,
    const float* __restrict__ wact)
{
    int idx = blockIdx.x * 128 + threadIdx.x;
    int b = idx >> 10;
    float cb = 0.f;
#pragma unroll
    for (int f = 0; f < Ee; f++) {
        float t = 0.f;
#pragma unroll
        for (int e = 0; e < Ee; e++) t += wall[f * Ee + e] * g_S[b * Ee + e];
        cb += wqr[f] * t;
    }
    float qv = cb;
#pragma unroll
    for (int e = 0; e < Ee; e++) {
        float t = 0.f;
#pragma unroll
        for (int f = 0; f < Ee; f++) t += wqr[Ee + f] * wact[f * Ee + e];
        qv += t * emb[(size_t)idx * Ee + e];
    }
    q[idx] = qv;
}

extern "C" void kernel_launch(void* const* d_in, const int* in_sizes, int n_in,
                              void* d_out, int out_size) {
    const float* features       = (const float*)d_in[0];
    const float* weights        = (const float*)d_in[1];
    const float* adjacency      = (const float*)d_in[2];
    const float* w_selected     = (const float*)d_in[3];
    const float* w_nbpriors     = (const float*)d_in[4];
    const float* w_nbweights    = (const float*)d_in[5];
    const float* w_nbweights_ew = (const float*)d_in[6];
    const float* w_q_reduc      = (const float*)d_in[7];
    const float* w_q_allembed   = (const float*)d_in[8];
    const float* w_q_action     = (const float*)d_in[9];

    float* out = (float*)d_out;
    float* q = out;                  // [B,N]
    float* emb_out = out + Bb * Nn;  // [B,N,E]

    cudaFuncSetAttribute(iter_kernel,
                         cudaFuncAttributeMaxDynamicSharedMemorySize, SMEM_DYN);

    conv_kernel<<<4096, 256>>>((const float4*)adjacency);
    colsum_kernel<<<dim3(NCH, Bb), 256>>>((const float4*)weights, w_nbpriors);
    base_kernel<<<32, 256>>>(features, w_selected, w_nbweights, w_nbweights_ew);

    dim3 ig(32, Bb);                 // 256 CTAs
    iter_kernel<<<ig, 256, SMEM_DYN>>>(0, emb_out, 0);  // iter 2
    iter_kernel<<<ig, 256, SMEM_DYN>>>(1, emb_out, 0);  // iter 3
    iter_kernel<<<ig, 256, SMEM_DYN>>>(0, emb_out, 0);  // iter 4
    iter_kernel<<<ig, 256, SMEM_DYN>>>(1, emb_out, 1);  // iter 5 (last)

    final_kernel<<<64, 128>>>(emb_out, q, w_q_reduc, w_q_allembed, w_q_action);
}

// round 16
// speedup vs baseline: 2.5311x; 1.3608x over previous
#include <cuda_runtime.h>
#include <cuda_bf16.h>
#include <cstdint>

#define Bb 8
#define Nn 1024
#define Ee 10
#define EPAD 16
#define NCH 32
#define NCTA 256

__device__ float g_Ppart[Bb * NCH * Nn];
__device__ float g_Mpart[Bb * NCH * Nn];
__device__ float g_base[Bb * Nn * Ee];
__device__ __nv_bfloat16 g_hbf[2][Bb * EPAD * Nn];   // h ping-pong [b][e(pad16)][i]
__device__ float g_S[Bb * Ee];
__device__ float g_wp[Ee * Ee];
__device__ int g_bar[4];

__device__ __forceinline__ uint32_t smem_u32(const void* p) {
    uint32_t a;
    asm("{ .reg .u64 t; cvta.to.shared.u64 t, %1; cvt.u32.u64 %0, t; }"
        : "=r"(a) : "l"(p));
    return a;
}

#define LDMX4(r0, r1, r2, r3, addr)                                           \
    asm volatile("ldmatrix.sync.aligned.m8n8.x4.shared.b16 {%0,%1,%2,%3}, [%4];" \
        : "=r"(r0), "=r"(r1), "=r"(r2), "=r"(r3) : "r"(addr))

__device__ __forceinline__ void mma_bf16(float* c, uint32_t a0, uint32_t a1,
                                         uint32_t a2, uint32_t a3,
                                         uint32_t b0, uint32_t b1) {
    asm volatile(
        "mma.sync.aligned.m16n8k16.row.col.f32.bf16.bf16.f32 "
        "{%0,%1,%2,%3}, {%4,%5,%6,%7}, {%8,%9}, {%0,%1,%2,%3};"
        : "+f"(c[0]), "+f"(c[1]), "+f"(c[2]), "+f"(c[3])
        : "r"(a0), "r"(a1), "r"(a2), "r"(a3), "r"(b0), "r"(b1));
}

// ---------------------------------------------------------------------------
// Colsum: P/M column sums of weights; stages Wp.
// ---------------------------------------------------------------------------
__global__ void __launch_bounds__(256) colsum_kernel(
    const float4* __restrict__ w4, const float* __restrict__ wp)
{
    int i4 = threadIdx.x, jc = blockIdx.x, b = blockIdx.y;
    if (jc == 0 && b == 0 && threadIdx.x < Ee * Ee)
        g_wp[threadIdx.x] = wp[threadIdx.x];

    const float4* p = w4 + ((size_t)(b * Nn + jc * 32) * 256) + i4;
    float4 sp = make_float4(0.f, 0.f, 0.f, 0.f);
    float4 sm = make_float4(0.f, 0.f, 0.f, 0.f);
#pragma unroll 8
    for (int j = 0; j < 32; j++) {
        float4 v = p[(size_t)j * 256];
        sp.x += fmaxf(v.x, 0.f); sm.x += fminf(v.x, 0.f);
        sp.y += fmaxf(v.y, 0.f); sm.y += fminf(v.y, 0.f);
        sp.z += fmaxf(v.z, 0.f); sm.z += fminf(v.z, 0.f);
        sp.w += fmaxf(v.w, 0.f); sm.w += fminf(v.w, 0.f);
    }
    ((float4*)g_Ppart)[(b * NCH + jc) * 256 + i4] = sp;
    ((float4*)g_Mpart)[(b * NCH + jc) * 256 + i4] = sm;
}

// ---------------------------------------------------------------------------
// Base: base[b,i,e], emb1=relu(base), h1=Wp@emb1 -> g_hbf[0]; zero pads,
// g_S and g_bar.
// ---------------------------------------------------------------------------
__global__ void __launch_bounds__(256) base_kernel(
    const float* __restrict__ feat,
    const float* __restrict__ ws,
    const float* __restrict__ wnb,
    const float* __restrict__ ew)
{
    int idx = blockIdx.x * 256 + threadIdx.x;
    int b = idx >> 10, i = idx & 1023;
    if (idx < Bb * Ee) g_S[idx] = 0.f;
    if (idx < 4) g_bar[idx] = 0;

    float P = 0.f, M = 0.f;
#pragma unroll 8
    for (int c = 0; c < NCH; c++) {
        P += g_Ppart[(b * NCH + c) * Nn + i];
        M += g_Mpart[(b * NCH + c) * Nn + i];
    }
    float f = feat[idx];

    float ewv[Ee];
#pragma unroll
    for (int e = 0; e < Ee; e++) ewv[e] = ew[e];

    float emb1[Ee];
#pragma unroll
    for (int e = 0; e < Ee; e++) {
        float cP = 0.f, cM = 0.f;
#pragma unroll
        for (int g = 0; g < Ee; g++) {
            float wv = wnb[e * Ee + g];
            cP += wv * fmaxf(ewv[g], 0.f);
            cM += wv * fminf(ewv[g], 0.f);
        }
        float basev = f * ws[e] + cP * P + cM * M;
        g_base[idx * Ee + e] = basev;
        emb1[e] = fmaxf(basev, 0.f);
    }
#pragma unroll
    for (int e = 0; e < Ee; e++) {
        float hv = 0.f;
#pragma unroll
        for (int g = 0; g < Ee; g++) hv += g_wp[e * Ee + g] * emb1[g];
        g_hbf[0][(b * EPAD + e) * Nn + i] = __float2bfloat16_rn(hv);
    }
#pragma unroll
    for (int e = Ee; e < EPAD; e++) {
        g_hbf[0][(b * EPAD + e) * Nn + i] = __float2bfloat16_rn(0.f);
        g_hbf[1][(b * EPAD + e) * Nn + i] = __float2bfloat16_rn(0.f);
    }
}

// ---------------------------------------------------------------------------
// Persistent iteration kernel (HMMA). grid (32 rowblocks, 8 b) = 256 CTAs,
// all co-resident (96 KB dyn smem -> 2 CTAs/SM -> 296 slots >= 256).
// Stage A once (fp32 -> bf16, swizzled, 64 KB), then 4 iterations with a
// software grid barrier between. Epilogue of iter 3 + q-output fused in.
// ---------------------------------------------------------------------------
#define SM_AS 0
#define SM_HS 65536
#define SMEM_DYN (65536 + 32768)

__global__ void __launch_bounds__(256) persist_kernel(
    const float* __restrict__ A,
    float* __restrict__ out,            // q [B,N] then emb [B,N,E]
    const float* __restrict__ wqr,
    const float* __restrict__ wall,
    const float* __restrict__ wact)
{
    extern __shared__ __align__(16) char smem[];
    __shared__ float wps[Ee * Ee];
    int rb = blockIdx.x, b = blockIdx.y;
    int tid = threadIdx.x;

    uint4* as4 = (uint4*)(smem + SM_AS);
    uint4* hs4 = (uint4*)(smem + SM_HS);

    // ---- stage A rows [rb*32, +32) fp32 -> bf16, chunked + swizzled ----
    const float4* Ag = (const float4*)(A + ((size_t)b * Nn + rb * 32) * Nn);
#pragma unroll
    for (int p = 0; p < 16; p++) {
        int idx = tid + p * 256;               // 0..4095 output uint4
        int r = idx >> 7, u7 = idx & 127;      // row, 8-col unit
        float4 v0 = Ag[(size_t)r * 256 + 2 * u7];
        float4 v1 = Ag[(size_t)r * 256 + 2 * u7 + 1];
        __nv_bfloat162 p0 = __floats2bfloat162_rn(v0.x, v0.y);
        __nv_bfloat162 p1 = __floats2bfloat162_rn(v0.z, v0.w);
        __nv_bfloat162 p2 = __floats2bfloat162_rn(v1.x, v1.y);
        __nv_bfloat162 p3 = __floats2bfloat162_rn(v1.z, v1.w);
        uint4 o;
        o.x = *reinterpret_cast<uint32_t*>(&p0);
        o.y = *reinterpret_cast<uint32_t*>(&p1);
        o.z = *reinterpret_cast<uint32_t*>(&p2);
        o.w = *reinterpret_cast<uint32_t*>(&p3);
        int ck = u7 >> 3, uu = u7 & 7;
        as4[ck * 256 + r * 8 + (uu ^ (r & 7))] = o;
    }
    if (tid < Ee * Ee) wps[tid] = g_wp[tid];

    int lane = tid & 31, w = tid >> 5;
    int wr = w & 1, wk = w >> 1;
    int half = lane >> 4, lr = lane & 15, l7 = lane & 7;
    uint32_t a_base = smem_u32(smem + SM_AS);
    uint32_t b_base = smem_u32(smem + SM_HS);
    uint32_t a_row = a_base + (uint32_t)((wr * 16 + lr) * 128);
    uint32_t b_row = b_base + (uint32_t)(lr * 2048);

    float embv[Ee];   // live across the last barrier (tid < 32)

    for (int it = 0; it < 4; it++) {
        int src = it & 1, last = (it == 3);

        // ---- stage h^T (L2-only loads; written by peers last iteration) ----
        const uint4* hb4 = (const uint4*)(g_hbf[src] + (size_t)b * EPAD * Nn);
#pragma unroll
        for (int p = 0; p < 8; p++) {
            int idx = tid + p * 256;
            int e = idx >> 7, u = idx & 127;
            hs4[e * 128 + (u ^ (e & 7))] = __ldcg(&hb4[idx]);
        }
        __syncthreads();

        // ---- mainloop: 16 k-steps per warp, sync-free ----
        float c0[4] = {0.f, 0.f, 0.f, 0.f};
        float c1[4] = {0.f, 0.f, 0.f, 0.f};
#pragma unroll
        for (int s = 0; s < 16; s++) {
            int sg = wk * 16 + s;
            int ck = sg >> 2, su = sg & 3;
            uint32_t aaddr = a_row + (uint32_t)(ck * 4096 +
                             (((2 * su + half) ^ l7) << 4));
            uint32_t baddr = b_row + (uint32_t)(((2 * sg + half) ^ l7) << 4);
            uint32_t a0, a1, a2, a3, r0, r1, r2, r3;
            LDMX4(a0, a1, a2, a3, aaddr);
            LDMX4(r0, r1, r2, r3, baddr);
            mma_bf16(c0, a0, a1, a2, a3, r0, r2);
            mma_bf16(c1, a0, a1, a2, a3, r1, r3);
        }

        // ---- combine k-slices through smem (reuse h region) ----
        __syncthreads();
        float* cs = (float*)(smem + SM_HS);
        {
            float* po = cs + (wk * 2 + wr) * 256;
            int g = lane >> 2, t = lane & 3;
            po[g * 16 + 2 * t] = c0[0];           po[g * 16 + 2 * t + 1] = c0[1];
            po[(g + 8) * 16 + 2 * t] = c0[2];     po[(g + 8) * 16 + 2 * t + 1] = c0[3];
            po[g * 16 + 8 + 2 * t] = c1[0];       po[g * 16 + 8 + 2 * t + 1] = c1[1];
            po[(g + 8) * 16 + 8 + 2 * t] = c1[2]; po[(g + 8) * 16 + 8 + 2 * t + 1] = c1[3];
        }
        __syncthreads();

        // ---- epilogue: thread t < 32 owns row t ----
        if (tid < 32) {
            int r = tid, i = rb * 32 + r;
            int wrr = r >> 4, rr = r & 15;
            const float* bp = g_base + ((size_t)(b * Nn) + i) * Ee;
#pragma unroll
            for (int e = 0; e < Ee; e++) {
                float v = bp[e];
#pragma unroll
                for (int k2 = 0; k2 < 4; k2++)
                    v += cs[(k2 * 2 + wrr) * 256 + rr * 16 + e];
                embv[e] = fmaxf(v, 0.f);
            }
            __nv_bfloat16* ho = g_hbf[src ^ 1] + (size_t)b * EPAD * Nn + i;
#pragma unroll
            for (int e = 0; e < Ee; e++) {
                float hv = 0.f;
#pragma unroll
                for (int f = 0; f < Ee; f++)
                    hv = fmaf(wps[e * Ee + f], embv[f], hv);
                ho[(size_t)e * Nn] = __float2bfloat16_rn(hv);
            }
            if (last) {
                float* emb_out = out + Bb * Nn;
#pragma unroll
                for (int e = 0; e < Ee; e++) {
                    emb_out[((size_t)(b * Nn) + i) * Ee + e] = embv[e];
                    float v = embv[e];
                    v += __shfl_xor_sync(0xffffffffu, v, 16);
                    v += __shfl_xor_sync(0xffffffffu, v, 8);
                    v += __shfl_xor_sync(0xffffffffu, v, 4);
                    v += __shfl_xor_sync(0xffffffffu, v, 2);
                    v += __shfl_xor_sync(0xffffffffu, v, 1);
                    if (lane == 0) atomicAdd(&g_S[b * Ee + e], v);
                }
            }
        }

        // ---- grid barrier ----
        if (tid == 0) {
            __threadfence();
            atomicAdd(&g_bar[it], 1);
            while (*(volatile int*)&g_bar[it] < NCTA) { }
        }
        __syncthreads();
    }

    // ---- fused final: q[b,i] = c_b + sum_e d_e * embv[e] ----
    if (tid < 32) {
        int i = rb * 32 + tid;
        float cb = 0.f;
#pragma unroll
        for (int f = 0; f < Ee; f++) {
            float t = 0.f;
#pragma unroll
            for (int e = 0; e < Ee; e++)
                t += wall[f * Ee + e] * __ldcg(&g_S[b * Ee + e]);
            cb += wqr[f] * t;
        }
        float qv = cb;
#pragma unroll
        for (int e = 0; e < Ee; e++) {
            float t = 0.f;
#pragma unroll
            for (int f = 0; f < Ee; f++) t += wqr[Ee + f] * wact[f * Ee + e];
            qv += t * embv[e];
        }
        out[b * Nn + i] = qv;
    }
}

extern "C" void kernel_launch(void* const* d_in, const int* in_sizes, int n_in,
                              void* d_out, int out_size) {
    const float* features       = (const float*)d_in[0];
    const float* weights        = (const float*)d_in[1];
    const float* adjacency      = (const float*)d_in[2];
    const float* w_selected     = (const float*)d_in[3];
    const float* w_nbpriors     = (const float*)d_in[4];
    const float* w_nbweights    = (const float*)d_in[5];
    const float* w_nbweights_ew = (const float*)d_in[6];
    const float* w_q_reduc      = (const float*)d_in[7];
    const float* w_q_allembed   = (const float*)d_in[8];
    const float* w_q_action     = (const float*)d_in[9];

    float* out = (float*)d_out;

    cudaFuncSetAttribute(persist_kernel,
                         cudaFuncAttributeMaxDynamicSharedMemorySize, SMEM_DYN);

    colsum_kernel<<<dim3(NCH, Bb), 256>>>((const float4*)weights, w_nbpriors);
    base_kernel<<<32, 256>>>(features, w_selected, w_nbweights, w_nbweights_ew);
    persist_kernel<<<dim3(32, Bb), 256, SMEM_DYN>>>(
        adjacency, out, w_q_reduc, w_q_allembed, w_q_action);
}

// round 17
// speedup vs baseline: 3.1902x; 1.2604x over previous
#include <cuda_runtime.h>
#include <cuda_bf16.h>
#include <cstdint>

#define Bb 8
#define Nn 1024
#define Ee 10
#define EPAD 16

__device__ float g_Ppart[Bb * 32 * Nn];
__device__ float g_Mpart[Bb * 32 * Nn];
__device__ __nv_bfloat16 g_hbf[2][Bb * EPAD * Nn];   // h ping-pong [b][e(pad16)][i]
__device__ float g_Spart[Bb * 32 * Ee];              // per-CTA embedding sums
__device__ int g_bar[6 * Bb];                        // monotonic ticket barriers

__device__ __forceinline__ uint32_t smem_u32(const void* p) {
    uint32_t a;
    asm("{ .reg .u64 t; cvta.to.shared.u64 t, %1; cvt.u32.u64 %0, t; }"
        : "=r"(a) : "l"(p));
    return a;
}

#define LDMX4(r0, r1, r2, r3, addr)                                           \
    asm volatile("ldmatrix.sync.aligned.m8n8.x4.shared.b16 {%0,%1,%2,%3}, [%4];" \
        : "=r"(r0), "=r"(r1), "=r"(r2), "=r"(r3) : "r"(addr))

__device__ __forceinline__ void mma_bf16(float* c, uint32_t a0, uint32_t a1,
                                         uint32_t a2, uint32_t a3,
                                         uint32_t b0, uint32_t b1) {
    asm volatile(
        "mma.sync.aligned.m16n8k16.row.col.f32.bf16.bf16.f32 "
        "{%0,%1,%2,%3}, {%4,%5,%6,%7}, {%8,%9}, {%0,%1,%2,%3};"
        : "+f"(c[0]), "+f"(c[1]), "+f"(c[2]), "+f"(c[3])
        : "r"(a0), "r"(a1), "r"(a2), "r"(a3), "r"(b0), "r"(b1));
}

// Per-batch barrier; counter is never reset (monotonic tickets survive graph
// replays: each launch adds exactly 32 per counter, waiters round up to the
// next multiple of 32).
__device__ __forceinline__ void batch_barrier(int k, int b, int tid) {
    if (tid == 0) {
        __threadfence();
        int* ctr = &g_bar[k * Bb + b];
        int ticket = atomicAdd(ctr, 1) + 1;
        int tgt = (ticket + 31) & ~31;
        while (*(volatile int*)ctr < tgt) { }
    }
    __syncthreads();
}

// ---------------------------------------------------------------------------
// The whole problem in one persistent kernel.
// grid (32 rowblocks, 8 batches) = 256 CTAs x 256 thr, 96 KB dyn smem
// -> 2 CTAs/SM, 296 slots >= 256: all co-resident, barriers deadlock-free.
// ---------------------------------------------------------------------------
#define SM_AS 0
#define SM_HS 65536
#define SMEM_DYN (65536 + 32768)

__global__ void __launch_bounds__(256, 2) persist_kernel(
    const float* __restrict__ A,
    const float* __restrict__ Wt,
    const float* __restrict__ feat,
    const float* __restrict__ ws,
    const float* __restrict__ wp,
    const float* __restrict__ wnb,
    const float* __restrict__ ew,
    const float* __restrict__ wqr,
    const float* __restrict__ wall,
    const float* __restrict__ wact,
    float* __restrict__ out)                 // q [B,N] then emb [B,N,E]
{
    extern __shared__ __align__(16) char smem[];
    __shared__ float wps[Ee * Ee];
    __shared__ float sbase[32][Ee];
    __shared__ float redP[8][32], redM[8][32];
    __shared__ float sS[Ee];
    int rb = blockIdx.x, b = blockIdx.y;
    int tid = threadIdx.x;

    uint4* as4 = (uint4*)(smem + SM_AS);
    uint4* hs4 = (uint4*)(smem + SM_HS);

    if (tid < Ee * Ee) wps[tid] = wp[tid];

    // ---- phase 0a: colsum partial for j-rows [rb*32, +32) of batch b ----
    {
        const float4* wsrc = (const float4*)Wt + (size_t)(b * Nn + rb * 32) * 256;
        float4 sp = make_float4(0.f, 0.f, 0.f, 0.f);
        float4 sm = make_float4(0.f, 0.f, 0.f, 0.f);
#pragma unroll 8
        for (int j = 0; j < 32; j++) {
            float4 v = wsrc[(size_t)j * 256 + tid];
            sp.x += fmaxf(v.x, 0.f); sm.x += fminf(v.x, 0.f);
            sp.y += fmaxf(v.y, 0.f); sm.y += fminf(v.y, 0.f);
            sp.z += fmaxf(v.z, 0.f); sm.z += fminf(v.z, 0.f);
            sp.w += fmaxf(v.w, 0.f); sm.w += fminf(v.w, 0.f);
        }
        ((float4*)g_Ppart)[(b * 32 + rb) * 256 + tid] = sp;
        ((float4*)g_Mpart)[(b * 32 + rb) * 256 + tid] = sm;
    }

    // ---- phase 0b: stage A rows [rb*32, +32) fp32 -> bf16, swizzled ----
    {
        const float4* Ag = (const float4*)(A + ((size_t)b * Nn + rb * 32) * Nn);
#pragma unroll
        for (int p = 0; p < 16; p++) {
            int idx = tid + p * 256;               // 0..4095 output uint4
            int r = idx >> 7, u7 = idx & 127;
            float4 v0 = Ag[(size_t)r * 256 + 2 * u7];
            float4 v1 = Ag[(size_t)r * 256 + 2 * u7 + 1];
            __nv_bfloat162 p0 = __floats2bfloat162_rn(v0.x, v0.y);
            __nv_bfloat162 p1 = __floats2bfloat162_rn(v0.z, v0.w);
            __nv_bfloat162 p2 = __floats2bfloat162_rn(v1.x, v1.y);
            __nv_bfloat162 p3 = __floats2bfloat162_rn(v1.z, v1.w);
            uint4 o;
            o.x = *reinterpret_cast<uint32_t*>(&p0);
            o.y = *reinterpret_cast<uint32_t*>(&p1);
            o.z = *reinterpret_cast<uint32_t*>(&p2);
            o.w = *reinterpret_cast<uint32_t*>(&p3);
            int ck = u7 >> 3, uu = u7 & 7;
            as4[ck * 256 + r * 8 + (uu ^ (r & 7))] = o;
        }
    }
    batch_barrier(0, b, tid);

    // ---- phase 1: reduce partials, base (smem), emb1, h1 + pads ----
    {
        int il = tid & 31, grp = tid >> 5;
        float P = 0.f, M = 0.f;
#pragma unroll
        for (int cc = 0; cc < 4; cc++) {
            int c = grp * 4 + cc;
            P += g_Ppart[(size_t)(b * 32 + c) * Nn + rb * 32 + il];
            M += g_Mpart[(size_t)(b * 32 + c) * Nn + rb * 32 + il];
        }
        redP[grp][il] = P; redM[grp][il] = M;
    }
    __syncthreads();
    if (tid < 32) {
        float P = 0.f, M = 0.f;
#pragma unroll
        for (int g2 = 0; g2 < 8; g2++) { P += redP[g2][tid]; M += redM[g2][tid]; }
        int i = rb * 32 + tid;
        float f = feat[b * Nn + i];
        float ewv[Ee];
#pragma unroll
        for (int e = 0; e < Ee; e++) ewv[e] = ew[e];
        float emb1[Ee];
#pragma unroll
        for (int e = 0; e < Ee; e++) {
            float cP = 0.f, cM = 0.f;
#pragma unroll
            for (int g2 = 0; g2 < Ee; g2++) {
                float wv = wnb[e * Ee + g2];
                cP += wv * fmaxf(ewv[g2], 0.f);
                cM += wv * fminf(ewv[g2], 0.f);
            }
            float bs = f * ws[e] + cP * P + cM * M;
            sbase[tid][e] = bs;
            emb1[e] = fmaxf(bs, 0.f);
        }
        __nv_bfloat16* h0 = g_hbf[0] + (size_t)b * EPAD * Nn + i;
#pragma unroll
        for (int e = 0; e < Ee; e++) {
            float hv = 0.f;
#pragma unroll
            for (int f2 = 0; f2 < Ee; f2++) hv = fmaf(wps[e * Ee + f2], emb1[f2], hv);
            h0[(size_t)e * Nn] = __float2bfloat16_rn(hv);
        }
#pragma unroll
        for (int e = Ee; e < EPAD; e++) {
            g_hbf[0][(size_t)(b * EPAD + e) * Nn + i] = __float2bfloat16_rn(0.f);
            g_hbf[1][(size_t)(b * EPAD + e) * Nn + i] = __float2bfloat16_rn(0.f);
        }
    }
    batch_barrier(1, b, tid);

    // ---- phases 2..5: four HMMA iterations ----
    int lane = tid & 31, w = tid >> 5;
    int wr = w & 1, wk = w >> 1;
    int half = lane >> 4, lr = lane & 15, l7 = lane & 7;
    uint32_t a_base = smem_u32(smem + SM_AS);
    uint32_t b_base = smem_u32(smem + SM_HS);
    uint32_t a_row = a_base + (uint32_t)((wr * 16 + lr) * 128);
    uint32_t b_row = b_base + (uint32_t)(lr * 2048);

    float embv[Ee];   // live across the last barrier (tid < 32)

    for (int it = 0; it < 4; it++) {
        int src = it & 1, last = (it == 3);

        const uint4* hb4 = (const uint4*)(g_hbf[src] + (size_t)b * EPAD * Nn);
#pragma unroll
        for (int p = 0; p < 8; p++) {
            int idx = tid + p * 256;
            int e = idx >> 7, u = idx & 127;
            hs4[e * 128 + (u ^ (e & 7))] = __ldcg(&hb4[idx]);
        }
        __syncthreads();

        float c0[4] = {0.f, 0.f, 0.f, 0.f};
        float c1[4] = {0.f, 0.f, 0.f, 0.f};
#pragma unroll
        for (int s = 0; s < 16; s++) {
            int sg = wk * 16 + s;
            int ck = sg >> 2, su = sg & 3;
            uint32_t aaddr = a_row + (uint32_t)(ck * 4096 +
                             (((2 * su + half) ^ l7) << 4));
            uint32_t baddr = b_row + (uint32_t)(((2 * sg + half) ^ l7) << 4);
            uint32_t a0, a1, a2, a3, r0, r1, r2, r3;
            LDMX4(a0, a1, a2, a3, aaddr);
            LDMX4(r0, r1, r2, r3, baddr);
            mma_bf16(c0, a0, a1, a2, a3, r0, r2);
            mma_bf16(c1, a0, a1, a2, a3, r1, r3);
        }

        __syncthreads();
        float* cs = (float*)(smem + SM_HS);
        {
            float* po = cs + (wk * 2 + wr) * 256;
            int g = lane >> 2, t = lane & 3;
            po[g * 16 + 2 * t] = c0[0];           po[g * 16 + 2 * t + 1] = c0[1];
            po[(g + 8) * 16 + 2 * t] = c0[2];     po[(g + 8) * 16 + 2 * t + 1] = c0[3];
            po[g * 16 + 8 + 2 * t] = c1[0];       po[g * 16 + 8 + 2 * t + 1] = c1[1];
            po[(g + 8) * 16 + 8 + 2 * t] = c1[2]; po[(g + 8) * 16 + 8 + 2 * t + 1] = c1[3];
        }
        __syncthreads();

        if (tid < 32) {
            int r = tid, i = rb * 32 + r;
            int wrr = r >> 4, rr = r & 15;
#pragma unroll
            for (int e = 0; e < Ee; e++) {
                float v = sbase[r][e];
#pragma unroll
                for (int k2 = 0; k2 < 4; k2++)
                    v += cs[(k2 * 2 + wrr) * 256 + rr * 16 + e];
                embv[e] = fmaxf(v, 0.f);
            }
            if (!last) {
                __nv_bfloat16* ho = g_hbf[src ^ 1] + (size_t)b * EPAD * Nn + i;
#pragma unroll
                for (int e = 0; e < Ee; e++) {
                    float hv = 0.f;
#pragma unroll
                    for (int f2 = 0; f2 < Ee; f2++)
                        hv = fmaf(wps[e * Ee + f2], embv[f2], hv);
                    ho[(size_t)e * Nn] = __float2bfloat16_rn(hv);
                }
            } else {
                float* emb_out = out + Bb * Nn;
#pragma unroll
                for (int e = 0; e < Ee; e++) {
                    emb_out[((size_t)(b * Nn) + i) * Ee + e] = embv[e];
                    float v = embv[e];
                    v += __shfl_xor_sync(0xffffffffu, v, 16);
                    v += __shfl_xor_sync(0xffffffffu, v, 8);
                    v += __shfl_xor_sync(0xffffffffu, v, 4);
                    v += __shfl_xor_sync(0xffffffffu, v, 2);
                    v += __shfl_xor_sync(0xffffffffu, v, 1);
                    if (lane == 0) g_Spart[(b * 32 + rb) * Ee + e] = v;
                }
            }
        }
        batch_barrier(2 + it, b, tid);
    }

    // ---- final: q[b,i] = c_b + sum_e d_e * embv[e] ----
    if (tid < Ee) {
        float S = 0.f;
#pragma unroll 8
        for (int c = 0; c < 32; c++)
            S += __ldcg(&g_Spart[(b * 32 + c) * Ee + tid]);
        sS[tid] = S;
    }
    __syncthreads();
    if (tid < 32) {
        int i = rb * 32 + tid;
        float cb = 0.f;
#pragma unroll
        for (int f = 0; f < Ee; f++) {
            float t = 0.f;
#pragma unroll
            for (int e = 0; e < Ee; e++) t += wall[f * Ee + e] * sS[e];
            cb += wqr[f] * t;
        }
        float qv = cb;
#pragma unroll
        for (int e = 0; e < Ee; e++) {
            float t = 0.f;
#pragma unroll
            for (int f = 0; f < Ee; f++) t += wqr[Ee + f] * wact[f * Ee + e];
            qv += t * embv[e];
        }
        out[b * Nn + i] = qv;
    }
}

extern "C" void kernel_launch(void* const* d_in, const int* in_sizes, int n_in,
                              void* d_out, int out_size) {
    const float* features       = (const float*)d_in[0];
    const float* weights        = (const float*)d_in[1];
    const float* adjacency      = (const float*)d_in[2];
    const float* w_selected     = (const float*)d_in[3];
    const float* w_nbpriors     = (const float*)d_in[4];
    const float* w_nbweights    = (const float*)d_in[5];
    const float* w_nbweights_ew = (const float*)d_in[6];
    const float* w_q_reduc      = (const float*)d_in[7];
    const float* w_q_allembed   = (const float*)d_in[8];
    const float* w_q_action     = (const float*)d_in[9];

    float* out = (float*)d_out;

    cudaFuncSetAttribute(persist_kernel,
                         cudaFuncAttributeMaxDynamicSharedMemorySize, SMEM_DYN);

    persist_kernel<<<dim3(32, Bb), 256, SMEM_DYN>>>(
        adjacency, weights, features, w_selected, w_nbpriors, w_nbweights,
        w_nbweights_ew, w_q_reduc, w_q_allembed, w_q_action, out);
}